// round 12
// baseline (speedup 1.0000x reference)
#include <cuda_runtime.h>
#include <cuda_fp16.h>
#include <math.h>
#include <stdint.h>

#define BB   8
#define LTOK 32768
#define DD   128
#define BSB  512
#define NBL  512
#define KW   6
#define NCH  64
#define SCALEF 0.08838834764831845f

// ---------------- device scratch ----------------
__device__ __align__(16) __half g_ph[(size_t)BB*LTOK*DD];   // prefix hi (fp16)
__device__ __align__(16) __half g_pl[(size_t)BB*LTOK*DD];   // prefix lo (fp16, sparse)
__device__ float    g_conv[(size_t)NBL*BSB*DD];
__device__ unsigned g_repr[NBL*DD];
__device__ float    g_as[NBL*DD];
__device__ float    g_ao[NBL*DD];
__device__ __align__(16) __half g_wh[KW*DD*DD];  // [k][o][i], fp16
// decoupled-lookback state
__device__ float    g_aggmax[BB*NCH], g_incmax[BB*NCH];
__device__ float    g_aggsum[BB*NCH], g_incsum[BB*NCH];
__device__ float    g_aggch[BB*NCH*DD], g_incch[BB*NCH*DD];
__device__ unsigned g_f1[BB*NCH], g_f2[BB*NCH], g_f3[BB*NCH];

// ---------------- helpers ----------------
__device__ __forceinline__ unsigned enc_f(float f) {
    unsigned u = __float_as_uint(f);
    return (u & 0x80000000u) ? ~u : (u | 0x80000000u);
}
__device__ __forceinline__ float dec_f(unsigned u) {
    u = (u & 0x80000000u) ? (u & 0x7fffffffu) : ~u;
    return __uint_as_float(u);
}
__device__ __forceinline__ uint32_t smem_u32(const void* p) {
    uint32_t a;
    asm("{ .reg .u64 t; cvta.to.shared.u64 t, %1; cvt.u32.u64 %0, t; }" : "=r"(a) : "l"(p));
    return a;
}
__device__ __forceinline__ void st_release(unsigned* p, unsigned v) {
    asm volatile("st.release.gpu.u32 [%0], %1;" :: "l"(p), "r"(v) : "memory");
}
__device__ __forceinline__ unsigned ld_acquire(unsigned* p) {
    unsigned v;
    asm volatile("ld.acquire.gpu.u32 %0, [%1];" : "=r"(v) : "l"(p) : "memory");
    return v;
}
__device__ __forceinline__ void ldsm_x4(uint32_t* r, uint32_t addr) {
    asm volatile("ldmatrix.sync.aligned.m8n8.x4.shared.b16 {%0,%1,%2,%3}, [%4];"
        : "=r"(r[0]), "=r"(r[1]), "=r"(r[2]), "=r"(r[3]) : "r"(addr));
}
__device__ __forceinline__ void mma16816(float* c, const uint32_t* a, uint32_t b0, uint32_t b1) {
    asm volatile(
        "mma.sync.aligned.m16n8k16.row.col.f32.f16.f16.f32 "
        "{%0,%1,%2,%3}, {%4,%5,%6,%7}, {%8,%9}, {%0,%1,%2,%3};"
        : "+f"(c[0]), "+f"(c[1]), "+f"(c[2]), "+f"(c[3])
        : "r"(a[0]), "r"(a[1]), "r"(a[2]), "r"(a[3]), "r"(b0), "r"(b1));
}
__device__ __forceinline__ void cpa16(uint32_t dst, const void* src) {
    asm volatile("cp.async.cg.shared.global [%0], [%1], 16;" :: "r"(dst), "l"(src) : "memory");
}
__device__ __forceinline__ void cpa16z(uint32_t dst, const void* src, int srcsize) {
    asm volatile("cp.async.cg.shared.global [%0], [%1], 16, %2;" :: "r"(dst), "l"(src), "r"(srcsize) : "memory");
}
#define CPA_COMMIT() asm volatile("cp.async.commit_group;" ::: "memory")
#define CPA_WAIT(n)  asm volatile("cp.async.wait_group %0;" :: "n"(n) : "memory")

// ---------------- K0: weights -> fp16 [k][o][i] + init repr/flags ----------------
__global__ void k_init(const float* __restrict__ cw) {
    int idx = blockIdx.x * blockDim.x + threadIdx.x;
    if (idx < KW*DD*DD) {
        int i = idx & 127;
        int r = idx >> 7;
        int o = r & 127;
        int kk = r >> 7;
        g_wh[idx] = __float2half(cw[o*768 + i*6 + kk]);
    }
    if (idx < NBL*DD) g_repr[idx] = 0u;
    if (idx < BB*NCH) { g_f1[idx] = 0u; g_f2[idx] = 0u; g_f3[idx] = 0u; }
}

// ---------------- 512-thread inclusive scan ----------------
template<bool MX>
__device__ __forceinline__ float iscan512(float v, float* ws) {
    int lane = threadIdx.x & 31, w = threadIdx.x >> 5;
    float x = v;
    #pragma unroll
    for (int o = 1; o < 32; o <<= 1) {
        float y = __shfl_up_sync(~0u, x, o);
        if (lane >= o) x = MX ? fmaxf(x, y) : (x + y);
    }
    if (lane == 31) ws[w] = x;
    __syncthreads();
    if (w == 0 && lane < 16) {
        float t = ws[lane];
        #pragma unroll
        for (int o = 1; o < 16; o <<= 1) {
            float y = __shfl_up_sync(0xFFFFu, t, o);
            if (lane >= o) t = MX ? fmaxf(t, y) : (t + y);
        }
        ws[lane] = t;
    }
    __syncthreads();
    if (w > 0) {
        float pre = ws[w-1];
        x = MX ? fmaxf(x, pre) : (x + pre);
    }
    return x;
}

// ---------------- K1: fused prefix pipeline ----------
// Reordered: sum-agg published right after cumsum; channel-partial pass runs
// BEFORE resolving the sum chain; sum walk (warp 8) and channel-vector walk
// (threads 0-127) run concurrently.
__global__ __launch_bounds__(512) void k_pre(const float* __restrict__ x,
                                             const float* __restrict__ w,
                                             const float* __restrict__ bl) {
    __shared__ float sl[512];
    __shared__ float se[512];
    __shared__ float sr[512];
    __shared__ float sP[512];
    __shared__ float sPre[128];
    __shared__ float sAgg[128];
    __shared__ float ws[16];
    __shared__ float sbc[2];
    int c = blockIdx.x, b = blockIdx.y;
    int bc = b*NCH + c;
    int tid = threadIdx.x, lane = tid & 31, wid = tid >> 5;
    size_t base = (size_t)b*LTOK + (size_t)c*BSB;

    // --- logits (x pass 1) ---
    float4 wv = *(const float4*)&w[lane*4];
    float bb = bl[0];
    for (int r0 = wid; r0 < 512; r0 += 16) {
        float4 xv = *(const float4*)&x[(base + r0)*DD + lane*4];
        float s = xv.x*wv.x + xv.y*wv.y + xv.z*wv.z + xv.w*wv.w;
        #pragma unroll
        for (int o = 16; o; o >>= 1) s += __shfl_xor_sync(~0u, s, o);
        if (lane == 0) {
            float z = s + bb;
            sl[r0] = z / (1.f + expf(-z));
        }
    }
    __syncthreads();

    // --- inclusive cummax + max lookback (serial walk) ---
    float l = sl[tid];
    float lm = iscan512<true>(l, ws);
    if (tid == 511) sbc[0] = lm;
    __syncthreads();
    if (tid == 0) {
        float own = sbc[0];
        g_aggmax[bc] = own;
        __threadfence();
        st_release(&g_f1[bc], 1);
        float pre = -INFINITY;
        int j = c - 1;
        while (j >= 0) {
            unsigned f;
            do { f = ld_acquire(&g_f1[b*NCH + j]); } while (f == 0);
            if (f == 2) { pre = fmaxf(pre, g_incmax[b*NCH + j]); break; }
            pre = fmaxf(pre, g_aggmax[b*NCH + j]);
            j--;
        }
        g_incmax[bc] = fmaxf(pre, own);
        __threadfence();
        st_release(&g_f1[bc], 2);
        sbc[1] = pre;
    }
    __syncthreads();
    float preM = sbc[1];

    // --- e = exp(l - runmax), cumsum; publish sum agg EARLY ---
    float M = fmaxf(lm, preM);
    float e = expf(l - M);
    se[tid] = e;
    float cs = iscan512<false>(e, ws);
    if (tid == 511) sbc[0] = cs;
    __syncthreads();
    if (tid == 0) {
        g_aggsum[bc] = sbc[0];
        __threadfence();
        st_release(&g_f2[bc], 1);
    }

    // --- channel partial sums of e*x (x pass 2) — overlaps others' lookbacks ---
    int d = tid & 127, q = tid >> 7;
    const float* xq = x + (base + q*128)*DD + d;
    {
        float acc = 0.f;
        #pragma unroll 4
        for (int t = 0; t < 128; t++) acc += se[q*128 + t] * xq[(size_t)t*DD];
        sP[q*128 + d] = acc;
    }
    __syncthreads();
    if (tid < 128) {
        float v = sP[d] + sP[128 + d] + sP[256 + d] + sP[384 + d];
        g_aggch[bc*DD + d] = v;
        sAgg[d] = v;
        __threadfence();
    }
    __syncthreads();
    if (tid == 0) st_release(&g_f3[bc], 1);

    // --- CONCURRENT: sum walk (tid 256) + channel vector walk (tids 0-127) ---
    if (tid == 256) {
        float own = sbc[0];
        float pre = 0.f;
        int j = c - 1;
        while (j >= 0) {
            unsigned f;
            do { f = ld_acquire(&g_f2[b*NCH + j]); } while (f == 0);
            if (f == 2) { pre += g_incsum[b*NCH + j]; break; }
            pre += g_aggsum[b*NCH + j];
            j--;
        }
        g_incsum[bc] = pre + own;
        __threadfence();
        st_release(&g_f2[bc], 2);
        sbc[1] = pre;
    }
    if (tid < 128) {
        float pre = 0.f;
        int j = c - 1;
        while (j >= 0) {
            unsigned f;
            do { f = ld_acquire(&g_f3[b*NCH + j]); } while (f == 0);
            if (f == 2) { pre += g_incch[(b*NCH + j)*DD + d]; break; }
            pre += g_aggch[(b*NCH + j)*DD + d];
            j--;
        }
        g_incch[bc*DD + d] = pre + sAgg[d];
        sPre[d] = pre;
        __threadfence();
    }
    __syncthreads();
    if (tid == 0) st_release(&g_f3[bc], 2);
    float preS = sbc[1];
    sr[tid] = 1.f / (cs + preS);
    __syncthreads();

    // --- final (x pass 3): prefix -> fp16 hi (+ lo only where attn_o reads) ---
    float run = sPre[d];
    for (int qq = 0; qq < q; qq++) run += sP[qq*128 + d];
    __half* ph = g_ph + (base + q*128)*DD + d;
    __half* pl = g_pl + (base + q*128)*DD + d;
    #pragma unroll 4
    for (int t = 0; t < 128; t++) {
        float xv = xq[(size_t)t*DD];
        run += se[q*128 + t] * xv;
        float pv = run * sr[q*128 + t] + xv;
        __half h = __float2half(pv);
        ph[(size_t)t*DD] = h;
        bool needpl = (q == 0) ? (t < 64) : (q == 3 ? (t >= 64) : false);
        if (needpl)
            pl[(size_t)t*DD] = __float2half(pv - __half2float(h));
    }
}

// ---------------- K4: conv1d fp16 single-pass, 2 CTAs/SM (unchanged R11) ----------
#define PITCH 272
#define A_OFF 0                  // 133*272 = 36176
#define W_OFF 36224
#define WSZ   34816
#define CONV_SMEM (W_OFF + 2*WSZ)    // 105856
__device__ __forceinline__ void conv_issueW(int k, uint32_t dstbase, int tid) {
    #pragma unroll
    for (int u = 0; u < 8; u++) {
        int t = tid + u*256;
        int o = t >> 4, cc = (t & 15) << 3;
        cpa16(dstbase + o*PITCH + cc*2, g_wh + (((size_t)(k*128 + o)) << 7) + cc);
    }
}
__global__ __launch_bounds__(256, 2) void k_conv(const float* __restrict__ cb) {
    extern __shared__ char sm[];
    uint32_t sb = smem_u32(sm);
    int tid = threadIdx.x, lane = tid & 31, wid = tid >> 5;
    int wm = wid >> 1, wn = wid & 1;
    int nb = blockIdx.x >> 2;
    int p0loc = (blockIdx.x & 3) << 7;
    int lr = lane & 15, lh = lane >> 4;

    float c[2][8][4];
    #pragma unroll
    for (int mt = 0; mt < 2; mt++)
        #pragma unroll
        for (int nt = 0; nt < 8; nt++)
            #pragma unroll
            for (int v = 0; v < 4; v++) c[mt][nt][v] = 0.f;

    for (int t = tid; t < 133*16; t += 256) {
        int r = t >> 4, cc = (t & 15) << 3;
        int qq = p0loc + r - 2;
        const void* src = g_ph;
        int sz = 0;
        if (qq >= 0 && qq < 512) {
            src = g_ph + ((((size_t)nb << 9) + qq) << 7) + cc;
            sz = 16;
        }
        cpa16z(sb + A_OFF + r*PITCH + cc*2, src, sz);
    }
    CPA_COMMIT();
    conv_issueW(0, sb + W_OFF, tid);
    CPA_COMMIT();
    conv_issueW(1, sb + W_OFF + WSZ, tid);
    CPA_COMMIT();
    CPA_WAIT(1);
    __syncthreads();
    #pragma unroll
    for (int s = 0; s < KW; s++) {
        uint32_t abase = sb + A_OFF + (wm*32 + s + lr)*PITCH + lh*16;
        uint32_t bbase = sb + W_OFF + (s & 1)*WSZ + (wn*64 + lr)*PITCH + lh*16;
        #pragma unroll
        for (int kc = 0; kc < 8; kc++) {
            uint32_t a[2][4];
            ldsm_x4(a[0], abase + kc*32);
            ldsm_x4(a[1], abase + kc*32 + 16*PITCH);
            #pragma unroll
            for (int ntp = 0; ntp < 4; ntp++) {
                uint32_t bf[4];
                ldsm_x4(bf, bbase + ntp*16*PITCH + kc*32);
                #pragma unroll
                for (int mt = 0; mt < 2; mt++) {
                    mma16816(c[mt][2*ntp],     a[mt], bf[0], bf[2]);
                    mma16816(c[mt][2*ntp + 1], a[mt], bf[1], bf[3]);
                }
            }
        }
        __syncthreads();
        if (s + 2 < KW) {
            conv_issueW(s + 2, sb + W_OFF + (s & 1)*WSZ, tid);
            CPA_COMMIT();
        }
        if (s + 1 < KW) {
            CPA_WAIT(1);
            __syncthreads();
        }
    }
    CPA_WAIT(0);
    __syncthreads();

    int pbase = nb*512 + p0loc + wm*32 + (lane >> 2);
    #pragma unroll
    for (int nt = 0; nt < 8; nt++) {
        int col = wn*64 + nt*8 + (lane & 3)*2;
        float2 b2 = *(const float2*)(cb + col);
        float mx = -INFINITY, my = -INFINITY;
        #pragma unroll
        for (int mt = 0; mt < 2; mt++) {
            float x0 = c[mt][nt][0] + b2.x, y0 = c[mt][nt][1] + b2.y;
            float x1 = c[mt][nt][2] + b2.x, y1 = c[mt][nt][3] + b2.y;
            int row = pbase + mt*16;
            *(float2*)(g_conv + ((size_t)row << 7) + col)       = make_float2(x0, y0);
            *(float2*)(g_conv + ((size_t)(row + 8) << 7) + col) = make_float2(x1, y1);
            mx = fmaxf(mx, fmaxf(x0, x1));
            my = fmaxf(my, fmaxf(y0, y1));
        }
        #pragma unroll
        for (int o = 4; o < 32; o <<= 1) {
            mx = fmaxf(mx, __shfl_xor_sync(~0u, mx, o));
            my = fmaxf(my, __shfl_xor_sync(~0u, my, o));
        }
        if (lane < 4) {
            int cg = wn*64 + nt*8 + lane*2;
            atomicMax(&g_repr[nb*DD + cg],     enc_f(mx));
            atomicMax(&g_repr[nb*DD + cg + 1], enc_f(my));
        }
    }
}

// ---------------- K6: a_s, smem-cached KV + online softmax (unchanged R11) ----------
#define ATTNS_SMEM (256*128*4)
__global__ __launch_bounds__(256, 1) void k_attn_s() {
    extern __shared__ float sv[];
    __shared__ float ss[256];
    __shared__ float red[256];
    int n = blockIdx.x, tid = threadIdx.x;
    int lane = tid & 31, wid = tid >> 5;
    int d = tid & 127, qh = tid >> 7;
    float4 q4;
    q4.x = dec_f(g_repr[n*DD + lane*4 + 0]);
    q4.y = dec_f(g_repr[n*DD + lane*4 + 1]);
    q4.z = dec_f(g_repr[n*DD + lane*4 + 2]);
    q4.w = dec_f(g_repr[n*DD + lane*4 + 3]);
    float M = -INFINITY, SUM = 0.f, acc = 0.f;
    for (int h = 0; h < 2; h++) {
        __syncthreads();
        const float* kv = g_conv + ((size_t)n*BSB + h*256)*DD;
        for (int i = tid*4; i < 256*128; i += 1024)
            *(float4*)&sv[i] = *(const float4*)&kv[i];
        __syncthreads();
        for (int j = wid; j < 256; j += 8) {
            float4 k4 = *(const float4*)&sv[j*DD + lane*4];
            float p = q4.x*k4.x + q4.y*k4.y + q4.z*k4.z + q4.w*k4.w;
            #pragma unroll
            for (int o = 16; o; o >>= 1) p += __shfl_xor_sync(~0u, p, o);
            if (lane == 0) ss[j] = p * SCALEF;
        }
        __syncthreads();
        red[tid] = ss[tid]; __syncthreads();
        for (int st = 128; st; st >>= 1) { if (tid < st) red[tid] = fmaxf(red[tid], red[tid+st]); __syncthreads(); }
        float Mn = fmaxf(M, red[0]);
        float sc = expf(M - Mn);
        acc *= sc; SUM *= sc; M = Mn;
        __syncthreads();
        float wgt = expf(ss[tid] - M);
        ss[tid] = wgt;
        red[tid] = wgt;
        __syncthreads();
        for (int st = 128; st; st >>= 1) { if (tid < st) red[tid] += red[tid+st]; __syncthreads(); }
        SUM += red[0];
        __syncthreads();
        #pragma unroll 4
        for (int t = 0; t < 128; t++) {
            int row = qh*128 + t;
            acc += ss[row] * sv[row*DD + d];
        }
    }
    __syncthreads();
    red[tid] = acc;
    __syncthreads();
    if (tid < 128) g_as[n*DD + tid] = (red[tid] + red[tid + 128]) / SUM;
}

// ---------------- K7: a_o (unchanged R11) ----------------
__global__ void k_attn_o() {
    int n = blockIdx.x, tid = threadIdx.x;
    int lane = tid & 31, w = tid >> 5;
    int bq = n >> 6, c = n & 63;
    __shared__ float s[128];
    __shared__ float red[128];
    float qa[4];
    #pragma unroll
    for (int q = 0; q < 4; q++) qa[q] = dec_f(g_repr[n*DD + lane*4 + q]);
    for (int j = w; j < 128; j += 4) {
        int tt = 448 + c*BSB + j; if (tt > LTOK-1) tt = LTOK-1;
        size_t ro = ((size_t)bq*LTOK + tt) << 7;
        float p = 0.f;
        #pragma unroll
        for (int q = 0; q < 4; q++) {
            int chn = lane*4 + q;
            float kvv = __half2float(g_ph[ro + chn]) + __half2float(g_pl[ro + chn]);
            p += qa[q] * kvv;
        }
        #pragma unroll
        for (int o = 16; o; o >>= 1) p += __shfl_xor_sync(~0u, p, o);
        if (lane == 0) s[j] = p * SCALEF;
    }
    __syncthreads();
    red[tid] = s[tid]; __syncthreads();
    for (int st = 64; st; st >>= 1) { if (tid < st) red[tid] = fmaxf(red[tid], red[tid+st]); __syncthreads(); }
    float M = red[0]; __syncthreads();
    float e = expf(s[tid] - M); s[tid] = e;
    red[tid] = e; __syncthreads();
    for (int st = 64; st; st >>= 1) { if (tid < st) red[tid] += red[tid+st]; __syncthreads(); }
    float SUM = red[0]; __syncthreads();
    float acc = 0.f;
    for (int j = 0; j < 128; j++) {
        int tt = 448 + c*BSB + j; if (tt > LTOK-1) tt = LTOK-1;
        size_t ro = ((size_t)bq*LTOK + tt) << 7;
        acc += s[j] * (__half2float(g_ph[ro + tid]) + __half2float(g_pl[ro + tid]));
    }
    g_ao[n*DD + tid] = acc / SUM;
}

// ---------------- K8: fusion GEMV ----------------
__global__ void k_fuse(const float* __restrict__ fw, const float* __restrict__ fb,
                       float* __restrict__ out, int out_size) {
    int n = blockIdx.x, o = threadIdx.x;
    __shared__ float f[384];
    f[o]       = g_as[n*DD + o];
    f[128 + o] = g_ao[n*DD + o];
    f[256 + o] = dec_f(g_repr[n*DD + o]);
    __syncthreads();
    float acc = fb[o];
    #pragma unroll 4
    for (int i = 0; i < 384; i++) acc += f[i] * fw[i*DD + o];
    for (int off = 0; off + NBL*DD <= out_size; off += NBL*DD)
        out[off + n*DD + o] = acc;
}

// ---------------- launch ----------------
extern "C" void kernel_launch(void* const* d_in, const int* in_sizes, int n_in,
                              void* d_out, int out_size) {
    const float* x        = (const float*)d_in[0];
    const float* w_lw     = (const float*)d_in[1];
    const float* b_lw     = (const float*)d_in[2];
    const float* conv_w   = (const float*)d_in[3];
    const float* conv_b   = (const float*)d_in[4];
    const float* fusion_w = (const float*)d_in[5];
    const float* fusion_b = (const float*)d_in[6];
    float* out = (float*)d_out;

    cudaFuncSetAttribute(k_conv, cudaFuncAttributeMaxDynamicSharedMemorySize, CONV_SMEM);
    cudaFuncSetAttribute(k_attn_s, cudaFuncAttributeMaxDynamicSharedMemorySize, ATTNS_SMEM);

    k_init<<<96, 1024>>>(conv_w);
    k_pre<<<dim3(NCH, BB), 512>>>(x, w_lw, b_lw);
    k_conv<<<2048, 256, CONV_SMEM>>>(conv_b);
    k_attn_s<<<NBL, 256, ATTNS_SMEM>>>();
    k_attn_o<<<NBL, 128>>>();
    k_fuse<<<NBL, 128>>>(fusion_w, fusion_b, out, out_size);
}

// round 13
// speedup vs baseline: 1.1122x; 1.1122x over previous
#include <cuda_runtime.h>
#include <cuda_fp16.h>
#include <math.h>
#include <stdint.h>

#define BB   8
#define LTOK 32768
#define DD   128
#define BSB  512
#define NBL  512
#define KW   6
#define NCH  64
#define SCALEF 0.08838834764831845f

// ---------------- device scratch ----------------
__device__ __align__(16) __half g_ph[(size_t)BB*LTOK*DD];   // prefix hi (fp16)
__device__ __align__(16) __half g_pl[(size_t)BB*LTOK*DD];   // prefix lo (fp16)
__device__ float    g_conv[(size_t)NBL*BSB*DD];
__device__ unsigned g_repr[NBL*DD];
__device__ float    g_as[NBL*DD];
__device__ float    g_ao[NBL*DD];
__device__ __align__(16) __half g_wh[KW*DD*DD];  // [k][o][i], fp16
// decoupled-lookback state
__device__ float    g_aggmax[BB*NCH], g_incmax[BB*NCH];
__device__ float    g_aggsum[BB*NCH], g_incsum[BB*NCH];
__device__ float    g_aggch[BB*NCH*DD], g_incch[BB*NCH*DD];
__device__ unsigned g_f1[BB*NCH], g_f2[BB*NCH], g_f3[BB*NCH];
// split-softmax partials (4 per block)
__device__ float    g_pm[NBL*4], g_psum[NBL*4];
__device__ float    g_pas[NBL*4*DD];

// ---------------- helpers ----------------
__device__ __forceinline__ unsigned enc_f(float f) {
    unsigned u = __float_as_uint(f);
    return (u & 0x80000000u) ? ~u : (u | 0x80000000u);
}
__device__ __forceinline__ float dec_f(unsigned u) {
    u = (u & 0x80000000u) ? (u & 0x7fffffffu) : ~u;
    return __uint_as_float(u);
}
__device__ __forceinline__ uint32_t smem_u32(const void* p) {
    uint32_t a;
    asm("{ .reg .u64 t; cvta.to.shared.u64 t, %1; cvt.u32.u64 %0, t; }" : "=r"(a) : "l"(p));
    return a;
}
__device__ __forceinline__ void st_release(unsigned* p, unsigned v) {
    asm volatile("st.release.gpu.u32 [%0], %1;" :: "l"(p), "r"(v) : "memory");
}
__device__ __forceinline__ unsigned ld_acquire(unsigned* p) {
    unsigned v;
    asm volatile("ld.acquire.gpu.u32 %0, [%1];" : "=r"(v) : "l"(p) : "memory");
    return v;
}
__device__ __forceinline__ void ldsm_x4(uint32_t* r, uint32_t addr) {
    asm volatile("ldmatrix.sync.aligned.m8n8.x4.shared.b16 {%0,%1,%2,%3}, [%4];"
        : "=r"(r[0]), "=r"(r[1]), "=r"(r[2]), "=r"(r[3]) : "r"(addr));
}
__device__ __forceinline__ void mma16816(float* c, const uint32_t* a, uint32_t b0, uint32_t b1) {
    asm volatile(
        "mma.sync.aligned.m16n8k16.row.col.f32.f16.f16.f32 "
        "{%0,%1,%2,%3}, {%4,%5,%6,%7}, {%8,%9}, {%0,%1,%2,%3};"
        : "+f"(c[0]), "+f"(c[1]), "+f"(c[2]), "+f"(c[3])
        : "r"(a[0]), "r"(a[1]), "r"(a[2]), "r"(a[3]), "r"(b0), "r"(b1));
}
__device__ __forceinline__ void cpa16(uint32_t dst, const void* src) {
    asm volatile("cp.async.cg.shared.global [%0], [%1], 16;" :: "r"(dst), "l"(src) : "memory");
}
__device__ __forceinline__ void cpa16z(uint32_t dst, const void* src, int srcsize) {
    asm volatile("cp.async.cg.shared.global [%0], [%1], 16, %2;" :: "r"(dst), "l"(src), "r"(srcsize) : "memory");
}
#define CPA_COMMIT() asm volatile("cp.async.commit_group;" ::: "memory")
#define CPA_WAIT(n)  asm volatile("cp.async.wait_group %0;" :: "n"(n) : "memory")

// ---------------- K0: weights -> fp16 [k][o][i] + init repr/flags ----------------
__global__ void k_init(const float* __restrict__ cw) {
    int idx = blockIdx.x * blockDim.x + threadIdx.x;
    if (idx < KW*DD*DD) {
        int i = idx & 127;
        int r = idx >> 7;
        int o = r & 127;
        int kk = r >> 7;
        g_wh[idx] = __float2half(cw[o*768 + i*6 + kk]);
    }
    if (idx < NBL*DD) g_repr[idx] = 0u;
    if (idx < BB*NCH) { g_f1[idx] = 0u; g_f2[idx] = 0u; g_f3[idx] = 0u; }
}

// ---------------- 512-thread inclusive scan ----------------
template<bool MX>
__device__ __forceinline__ float iscan512(float v, float* ws) {
    int lane = threadIdx.x & 31, w = threadIdx.x >> 5;
    float x = v;
    #pragma unroll
    for (int o = 1; o < 32; o <<= 1) {
        float y = __shfl_up_sync(~0u, x, o);
        if (lane >= o) x = MX ? fmaxf(x, y) : (x + y);
    }
    if (lane == 31) ws[w] = x;
    __syncthreads();
    if (w == 0 && lane < 16) {
        float t = ws[lane];
        #pragma unroll
        for (int o = 1; o < 16; o <<= 1) {
            float y = __shfl_up_sync(0xFFFFu, t, o);
            if (lane >= o) t = MX ? fmaxf(t, y) : (t + y);
        }
        ws[lane] = t;
    }
    __syncthreads();
    if (w > 0) {
        float pre = ws[w-1];
        x = MX ? fmaxf(x, pre) : (x + pre);
    }
    return x;
}

// ---------------- K1: fused prefix pipeline (R11 version, reverted) ----------
__global__ __launch_bounds__(512) void k_pre(const float* __restrict__ x,
                                             const float* __restrict__ w,
                                             const float* __restrict__ bl) {
    __shared__ float sl[512];
    __shared__ float se[512];
    __shared__ float sr[512];
    __shared__ float sP[512];
    __shared__ float sPre[128];
    __shared__ float sAgg[128];
    __shared__ float ws[16];
    __shared__ float sbc[2];
    int c = blockIdx.x, b = blockIdx.y;
    int bc = b*NCH + c;
    int tid = threadIdx.x, lane = tid & 31, wid = tid >> 5;
    size_t base = (size_t)b*LTOK + (size_t)c*BSB;

    // --- logits ---
    float4 wv = *(const float4*)&w[lane*4];
    float bb = bl[0];
    for (int r0 = wid; r0 < 512; r0 += 16) {
        float4 xv = *(const float4*)&x[(base + r0)*DD + lane*4];
        float s = xv.x*wv.x + xv.y*wv.y + xv.z*wv.z + xv.w*wv.w;
        #pragma unroll
        for (int o = 16; o; o >>= 1) s += __shfl_xor_sync(~0u, s, o);
        if (lane == 0) {
            float z = s + bb;
            sl[r0] = z / (1.f + expf(-z));
        }
    }
    __syncthreads();

    // --- inclusive cummax + max lookback ---
    float l = sl[tid];
    float lm = iscan512<true>(l, ws);
    if (tid == 511) sbc[0] = lm;
    __syncthreads();
    if (tid == 0) {
        float own = sbc[0];
        g_aggmax[bc] = own;
        __threadfence();
        st_release(&g_f1[bc], 1);
        float pre = -INFINITY;
        int j = c - 1;
        while (j >= 0) {
            unsigned f;
            do { f = ld_acquire(&g_f1[b*NCH + j]); } while (f == 0);
            if (f == 2) { pre = fmaxf(pre, g_incmax[b*NCH + j]); break; }
            pre = fmaxf(pre, g_aggmax[b*NCH + j]);
            j--;
        }
        g_incmax[bc] = fmaxf(pre, own);
        __threadfence();
        st_release(&g_f1[bc], 2);
        sbc[1] = pre;
    }
    __syncthreads();
    float preM = sbc[1];

    // --- e = exp(l - runmax), cumsum + sum lookback ---
    float M = fmaxf(lm, preM);
    float e = expf(l - M);
    se[tid] = e;
    float cs = iscan512<false>(e, ws);
    if (tid == 511) sbc[0] = cs;
    __syncthreads();
    if (tid == 0) {
        float own = sbc[0];
        g_aggsum[bc] = own;
        __threadfence();
        st_release(&g_f2[bc], 1);
        float pre = 0.f;
        int j = c - 1;
        while (j >= 0) {
            unsigned f;
            do { f = ld_acquire(&g_f2[b*NCH + j]); } while (f == 0);
            if (f == 2) { pre += g_incsum[b*NCH + j]; break; }
            pre += g_aggsum[b*NCH + j];
            j--;
        }
        g_incsum[bc] = pre + own;
        __threadfence();
        st_release(&g_f2[bc], 2);
        sbc[1] = pre;
    }
    __syncthreads();
    float preS = sbc[1];
    sr[tid] = 1.f / (cs + preS);
    __syncthreads();

    // --- channel partial sums of e*x ---
    int d = tid & 127, q = tid >> 7;
    const float* xq = x + (base + q*128)*DD + d;
    {
        float acc = 0.f;
        #pragma unroll 4
        for (int t = 0; t < 128; t++) acc += se[q*128 + t] * xq[(size_t)t*DD];
        sP[q*128 + d] = acc;
    }
    __syncthreads();
    if (tid < 128) {
        float v = sP[d] + sP[128 + d] + sP[256 + d] + sP[384 + d];
        g_aggch[bc*DD + d] = v;
        sAgg[d] = v;
        __threadfence();
    }
    __syncthreads();
    if (tid == 0) st_release(&g_f3[bc], 1);

    // --- channel vector lookback ---
    if (tid < 128) {
        float pre = 0.f;
        int j = c - 1;
        while (j >= 0) {
            unsigned f;
            do { f = ld_acquire(&g_f3[b*NCH + j]); } while (f == 0);
            if (f == 2) { pre += g_incch[(b*NCH + j)*DD + d]; break; }
            pre += g_aggch[(b*NCH + j)*DD + d];
            j--;
        }
        g_incch[bc*DD + d] = pre + sAgg[d];
        sPre[d] = pre;
        __threadfence();
    }
    __syncthreads();
    if (tid == 0) st_release(&g_f3[bc], 2);

    // --- final: prefix = cumsum(e*x)*r + x -> fp16 hi/lo ---
    float run = sPre[d];
    for (int qq = 0; qq < q; qq++) run += sP[qq*128 + d];
    __half* ph = g_ph + (base + q*128)*DD + d;
    __half* pl = g_pl + (base + q*128)*DD + d;
    #pragma unroll 4
    for (int t = 0; t < 128; t++) {
        float xv = xq[(size_t)t*DD];
        run += se[q*128 + t] * xv;
        float pv = run * sr[q*128 + t] + xv;
        __half h = __float2half(pv);
        ph[(size_t)t*DD] = h;
        pl[(size_t)t*DD] = __float2half(pv - __half2float(h));
    }
}

// ---------------- K4: conv1d fp16 single-pass, 2 CTAs/SM (unchanged R11) ----------
#define PITCH 272
#define A_OFF 0
#define W_OFF 36224
#define WSZ   34816
#define CONV_SMEM (W_OFF + 2*WSZ)    // 105856
__device__ __forceinline__ void conv_issueW(int k, uint32_t dstbase, int tid) {
    #pragma unroll
    for (int u = 0; u < 8; u++) {
        int t = tid + u*256;
        int o = t >> 4, cc = (t & 15) << 3;
        cpa16(dstbase + o*PITCH + cc*2, g_wh + (((size_t)(k*128 + o)) << 7) + cc);
    }
}
__global__ __launch_bounds__(256, 2) void k_conv(const float* __restrict__ cb) {
    extern __shared__ char sm[];
    uint32_t sb = smem_u32(sm);
    int tid = threadIdx.x, lane = tid & 31, wid = tid >> 5;
    int wm = wid >> 1, wn = wid & 1;
    int nb = blockIdx.x >> 2;
    int p0loc = (blockIdx.x & 3) << 7;
    int lr = lane & 15, lh = lane >> 4;

    float c[2][8][4];
    #pragma unroll
    for (int mt = 0; mt < 2; mt++)
        #pragma unroll
        for (int nt = 0; nt < 8; nt++)
            #pragma unroll
            for (int v = 0; v < 4; v++) c[mt][nt][v] = 0.f;

    for (int t = tid; t < 133*16; t += 256) {
        int r = t >> 4, cc = (t & 15) << 3;
        int qq = p0loc + r - 2;
        const void* src = g_ph;
        int sz = 0;
        if (qq >= 0 && qq < 512) {
            src = g_ph + ((((size_t)nb << 9) + qq) << 7) + cc;
            sz = 16;
        }
        cpa16z(sb + A_OFF + r*PITCH + cc*2, src, sz);
    }
    CPA_COMMIT();
    conv_issueW(0, sb + W_OFF, tid);
    CPA_COMMIT();
    conv_issueW(1, sb + W_OFF + WSZ, tid);
    CPA_COMMIT();
    CPA_WAIT(1);
    __syncthreads();
    #pragma unroll
    for (int s = 0; s < KW; s++) {
        uint32_t abase = sb + A_OFF + (wm*32 + s + lr)*PITCH + lh*16;
        uint32_t bbase = sb + W_OFF + (s & 1)*WSZ + (wn*64 + lr)*PITCH + lh*16;
        #pragma unroll
        for (int kc = 0; kc < 8; kc++) {
            uint32_t a[2][4];
            ldsm_x4(a[0], abase + kc*32);
            ldsm_x4(a[1], abase + kc*32 + 16*PITCH);
            #pragma unroll
            for (int ntp = 0; ntp < 4; ntp++) {
                uint32_t bf[4];
                ldsm_x4(bf, bbase + ntp*16*PITCH + kc*32);
                #pragma unroll
                for (int mt = 0; mt < 2; mt++) {
                    mma16816(c[mt][2*ntp],     a[mt], bf[0], bf[2]);
                    mma16816(c[mt][2*ntp + 1], a[mt], bf[1], bf[3]);
                }
            }
        }
        __syncthreads();
        if (s + 2 < KW) {
            conv_issueW(s + 2, sb + W_OFF + (s & 1)*WSZ, tid);
            CPA_COMMIT();
        }
        if (s + 1 < KW) {
            CPA_WAIT(1);
            __syncthreads();
        }
    }
    CPA_WAIT(0);
    __syncthreads();

    int pbase = nb*512 + p0loc + wm*32 + (lane >> 2);
    #pragma unroll
    for (int nt = 0; nt < 8; nt++) {
        int col = wn*64 + nt*8 + (lane & 3)*2;
        float2 b2 = *(const float2*)(cb + col);
        float mx = -INFINITY, my = -INFINITY;
        #pragma unroll
        for (int mt = 0; mt < 2; mt++) {
            float x0 = c[mt][nt][0] + b2.x, y0 = c[mt][nt][1] + b2.y;
            float x1 = c[mt][nt][2] + b2.x, y1 = c[mt][nt][3] + b2.y;
            int row = pbase + mt*16;
            *(float2*)(g_conv + ((size_t)row << 7) + col)       = make_float2(x0, y0);
            *(float2*)(g_conv + ((size_t)(row + 8) << 7) + col) = make_float2(x1, y1);
            mx = fmaxf(mx, fmaxf(x0, x1));
            my = fmaxf(my, fmaxf(y0, y1));
        }
        #pragma unroll
        for (int o = 4; o < 32; o <<= 1) {
            mx = fmaxf(mx, __shfl_xor_sync(~0u, mx, o));
            my = fmaxf(my, __shfl_xor_sync(~0u, my, o));
        }
        if (lane < 4) {
            int cg = wn*64 + nt*8 + lane*2;
            atomicMax(&g_repr[nb*DD + cg],     enc_f(mx));
            atomicMax(&g_repr[nb*DD + cg + 1], enc_f(my));
        }
    }
}

// ---------------- K6a: a_s phase A — split softmax partials ----------------
// grid = NBL*4 (block n, quarter qq). 256 threads, 64 KB smem (128 rows fp32).
#define ATTNS_SMEM (128*128*4)
__global__ __launch_bounds__(256, 3) void k_attn_s1() {
    extern __shared__ float sv[];      // 128 rows x 128 ch
    __shared__ float ss[128];
    __shared__ float red[256];
    int id = blockIdx.x;
    int n = id >> 2, qq = id & 3;
    int tid = threadIdx.x, lane = tid & 31, wid = tid >> 5;
    int d = tid & 127, h = tid >> 7;
    float4 q4;
    q4.x = dec_f(g_repr[n*DD + lane*4 + 0]);
    q4.y = dec_f(g_repr[n*DD + lane*4 + 1]);
    q4.z = dec_f(g_repr[n*DD + lane*4 + 2]);
    q4.w = dec_f(g_repr[n*DD + lane*4 + 3]);
    const float* kv = g_conv + ((size_t)n*BSB + qq*128)*DD;
    for (int i = tid*4; i < 128*128; i += 1024)
        *(float4*)&sv[i] = *(const float4*)&kv[i];
    __syncthreads();
    // scores: 8 warps x 16 rows
    for (int j = wid; j < 128; j += 8) {
        float4 k4 = *(const float4*)&sv[j*DD + lane*4];
        float p = q4.x*k4.x + q4.y*k4.y + q4.z*k4.z + q4.w*k4.w;
        #pragma unroll
        for (int o = 16; o; o >>= 1) p += __shfl_xor_sync(~0u, p, o);
        if (lane == 0) ss[j] = p * SCALEF;
    }
    __syncthreads();
    // local max
    red[tid] = (tid < 128) ? ss[tid] : -INFINITY;
    __syncthreads();
    for (int st = 128; st; st >>= 1) { if (tid < st) red[tid] = fmaxf(red[tid], red[tid+st]); __syncthreads(); }
    float m = red[0];
    __syncthreads();
    // exp + local sum
    float ev = 0.f;
    if (tid < 128) { ev = expf(ss[tid] - m); ss[tid] = ev; }
    red[tid] = ev;
    __syncthreads();
    for (int st = 128; st; st >>= 1) { if (tid < st) red[tid] += red[tid+st]; __syncthreads(); }
    float S = red[0];
    __syncthreads();
    // AV partial: thread (d,h) sums 64 rows
    float acc = 0.f;
    #pragma unroll 4
    for (int t = 0; t < 64; t++) {
        int row = h*64 + t;
        acc += ss[row] * sv[row*DD + d];
    }
    red[tid] = acc;
    __syncthreads();
    if (tid < 128) g_pas[id*DD + tid] = red[tid] + red[tid + 128];
    if (tid == 0) { g_pm[id] = m; g_psum[id] = S; }
}

// ---------------- K6b: a_s phase B — combine 4 partials ----------------
__global__ void k_attn_s2() {
    int n = blockIdx.x, d = threadIdx.x;   // 128 threads
    float m0 = g_pm[n*4+0], m1 = g_pm[n*4+1], m2 = g_pm[n*4+2], m3 = g_pm[n*4+3];
    float M = fmaxf(fmaxf(m0, m1), fmaxf(m2, m3));
    float w0 = expf(m0 - M), w1 = expf(m1 - M), w2 = expf(m2 - M), w3 = expf(m3 - M);
    float S = w0*g_psum[n*4+0] + w1*g_psum[n*4+1] + w2*g_psum[n*4+2] + w3*g_psum[n*4+3];
    float v = w0*g_pas[(n*4+0)*DD + d] + w1*g_pas[(n*4+1)*DD + d]
            + w2*g_pas[(n*4+2)*DD + d] + w3*g_pas[(n*4+3)*DD + d];
    g_as[n*DD + d] = v / S;
}

// ---------------- K7: a_o (unchanged R11) ----------------
__global__ void k_attn_o() {
    int n = blockIdx.x, tid = threadIdx.x;
    int lane = tid & 31, w = tid >> 5;
    int bq = n >> 6, c = n & 63;
    __shared__ float s[128];
    __shared__ float red[128];
    float qa[4];
    #pragma unroll
    for (int q = 0; q < 4; q++) qa[q] = dec_f(g_repr[n*DD + lane*4 + q]);
    for (int j = w; j < 128; j += 4) {
        int tt = 448 + c*BSB + j; if (tt > LTOK-1) tt = LTOK-1;
        size_t ro = ((size_t)bq*LTOK + tt) << 7;
        float p = 0.f;
        #pragma unroll
        for (int q = 0; q < 4; q++) {
            int chn = lane*4 + q;
            float kvv = __half2float(g_ph[ro + chn]) + __half2float(g_pl[ro + chn]);
            p += qa[q] * kvv;
        }
        #pragma unroll
        for (int o = 16; o; o >>= 1) p += __shfl_xor_sync(~0u, p, o);
        if (lane == 0) s[j] = p * SCALEF;
    }
    __syncthreads();
    red[tid] = s[tid]; __syncthreads();
    for (int st = 64; st; st >>= 1) { if (tid < st) red[tid] = fmaxf(red[tid], red[tid+st]); __syncthreads(); }
    float M = red[0]; __syncthreads();
    float e = expf(s[tid] - M); s[tid] = e;
    red[tid] = e; __syncthreads();
    for (int st = 64; st; st >>= 1) { if (tid < st) red[tid] += red[tid+st]; __syncthreads(); }
    float SUM = red[0]; __syncthreads();
    float acc = 0.f;
    for (int j = 0; j < 128; j++) {
        int tt = 448 + c*BSB + j; if (tt > LTOK-1) tt = LTOK-1;
        size_t ro = ((size_t)bq*LTOK + tt) << 7;
        acc += s[j] * (__half2float(g_ph[ro + tid]) + __half2float(g_pl[ro + tid]));
    }
    g_ao[n*DD + tid] = acc / SUM;
}

// ---------------- K8: fusion GEMV ----------------
__global__ void k_fuse(const float* __restrict__ fw, const float* __restrict__ fb,
                       float* __restrict__ out, int out_size) {
    int n = blockIdx.x, o = threadIdx.x;
    __shared__ float f[384];
    f[o]       = g_as[n*DD + o];
    f[128 + o] = g_ao[n*DD + o];
    f[256 + o] = dec_f(g_repr[n*DD + o]);
    __syncthreads();
    float acc = fb[o];
    #pragma unroll 4
    for (int i = 0; i < 384; i++) acc += f[i] * fw[i*DD + o];
    for (int off = 0; off + NBL*DD <= out_size; off += NBL*DD)
        out[off + n*DD + o] = acc;
}

// ---------------- launch ----------------
extern "C" void kernel_launch(void* const* d_in, const int* in_sizes, int n_in,
                              void* d_out, int out_size) {
    const float* x        = (const float*)d_in[0];
    const float* w_lw     = (const float*)d_in[1];
    const float* b_lw     = (const float*)d_in[2];
    const float* conv_w   = (const float*)d_in[3];
    const float* conv_b   = (const float*)d_in[4];
    const float* fusion_w = (const float*)d_in[5];
    const float* fusion_b = (const float*)d_in[6];
    float* out = (float*)d_out;

    cudaFuncSetAttribute(k_conv, cudaFuncAttributeMaxDynamicSharedMemorySize, CONV_SMEM);
    cudaFuncSetAttribute(k_attn_s1, cudaFuncAttributeMaxDynamicSharedMemorySize, ATTNS_SMEM);

    k_init<<<96, 1024>>>(conv_w);
    k_pre<<<dim3(NCH, BB), 512>>>(x, w_lw, b_lw);
    k_conv<<<2048, 256, CONV_SMEM>>>(conv_b);
    k_attn_s1<<<NBL*4, 256, ATTNS_SMEM>>>();
    k_attn_s2<<<NBL, 128>>>();
    k_attn_o<<<NBL, 128>>>();
    k_fuse<<<NBL, 128>>>(fusion_w, fusion_b, out, out_size);
}

// round 14
// speedup vs baseline: 1.2875x; 1.1577x over previous
#include <cuda_runtime.h>
#include <cuda_fp16.h>
#include <math.h>
#include <stdint.h>

#define BB   8
#define LTOK 32768
#define DD   128
#define BSB  512
#define NBL  512
#define KW   6
#define NCH  64
#define SCALEF 0.08838834764831845f

// ---------------- device scratch ----------------
__device__ __align__(16) __half g_ph[(size_t)BB*LTOK*DD];   // prefix hi (fp16)
__device__ __align__(16) __half g_pl[(size_t)BB*LTOK*DD];   // prefix lo (fp16)
__device__ __align__(16) __half g_convh[(size_t)NBL*BSB*DD]; // conv out (fp16)
__device__ unsigned g_repr[NBL*DD];
__device__ __align__(16) __half g_wh[KW*DD*DD];  // [k][o][i], fp16
// decoupled-lookback state
__device__ float    g_aggmax[BB*NCH], g_incmax[BB*NCH];
__device__ float    g_aggsum[BB*NCH], g_incsum[BB*NCH];
__device__ float    g_aggch[BB*NCH*DD], g_incch[BB*NCH*DD];
__device__ unsigned g_f1[BB*NCH], g_f2[BB*NCH], g_f3[BB*NCH];
// split-softmax partials (4 per block)
__device__ float    g_pm[NBL*4], g_psum[NBL*4];
__device__ float    g_pas[NBL*4*DD];

// ---------------- helpers ----------------
__device__ __forceinline__ unsigned enc_f(float f) {
    unsigned u = __float_as_uint(f);
    return (u & 0x80000000u) ? ~u : (u | 0x80000000u);
}
__device__ __forceinline__ float dec_f(unsigned u) {
    u = (u & 0x80000000u) ? (u & 0x7fffffffu) : ~u;
    return __uint_as_float(u);
}
__device__ __forceinline__ uint32_t smem_u32(const void* p) {
    uint32_t a;
    asm("{ .reg .u64 t; cvta.to.shared.u64 t, %1; cvt.u32.u64 %0, t; }" : "=r"(a) : "l"(p));
    return a;
}
__device__ __forceinline__ void st_release(unsigned* p, unsigned v) {
    asm volatile("st.release.gpu.u32 [%0], %1;" :: "l"(p), "r"(v) : "memory");
}
__device__ __forceinline__ unsigned ld_acquire(unsigned* p) {
    unsigned v;
    asm volatile("ld.acquire.gpu.u32 %0, [%1];" : "=r"(v) : "l"(p) : "memory");
    return v;
}
__device__ __forceinline__ void ldsm_x4(uint32_t* r, uint32_t addr) {
    asm volatile("ldmatrix.sync.aligned.m8n8.x4.shared.b16 {%0,%1,%2,%3}, [%4];"
        : "=r"(r[0]), "=r"(r[1]), "=r"(r[2]), "=r"(r[3]) : "r"(addr));
}
__device__ __forceinline__ void mma16816(float* c, const uint32_t* a, uint32_t b0, uint32_t b1) {
    asm volatile(
        "mma.sync.aligned.m16n8k16.row.col.f32.f16.f16.f32 "
        "{%0,%1,%2,%3}, {%4,%5,%6,%7}, {%8,%9}, {%0,%1,%2,%3};"
        : "+f"(c[0]), "+f"(c[1]), "+f"(c[2]), "+f"(c[3])
        : "r"(a[0]), "r"(a[1]), "r"(a[2]), "r"(a[3]), "r"(b0), "r"(b1));
}
__device__ __forceinline__ void cpa16(uint32_t dst, const void* src) {
    asm volatile("cp.async.cg.shared.global [%0], [%1], 16;" :: "r"(dst), "l"(src) : "memory");
}
__device__ __forceinline__ void cpa16z(uint32_t dst, const void* src, int srcsize) {
    asm volatile("cp.async.cg.shared.global [%0], [%1], 16, %2;" :: "r"(dst), "l"(src), "r"(srcsize) : "memory");
}
#define CPA_COMMIT() asm volatile("cp.async.commit_group;" ::: "memory")
#define CPA_WAIT(n)  asm volatile("cp.async.wait_group %0;" :: "n"(n) : "memory")

// ---------------- K0: weights -> fp16 [k][o][i] + init repr/flags ----------------
__global__ void k_init(const float* __restrict__ cw) {
    int idx = blockIdx.x * blockDim.x + threadIdx.x;
    if (idx < KW*DD*DD) {
        int i = idx & 127;
        int r = idx >> 7;
        int o = r & 127;
        int kk = r >> 7;
        g_wh[idx] = __float2half(cw[o*768 + i*6 + kk]);
    }
    if (idx < NBL*DD) g_repr[idx] = 0u;
    if (idx < BB*NCH) { g_f1[idx] = 0u; g_f2[idx] = 0u; g_f3[idx] = 0u; }
}

// ---------------- 512-thread inclusive scan ----------------
template<bool MX>
__device__ __forceinline__ float iscan512(float v, float* ws) {
    int lane = threadIdx.x & 31, w = threadIdx.x >> 5;
    float x = v;
    #pragma unroll
    for (int o = 1; o < 32; o <<= 1) {
        float y = __shfl_up_sync(~0u, x, o);
        if (lane >= o) x = MX ? fmaxf(x, y) : (x + y);
    }
    if (lane == 31) ws[w] = x;
    __syncthreads();
    if (w == 0 && lane < 16) {
        float t = ws[lane];
        #pragma unroll
        for (int o = 1; o < 16; o <<= 1) {
            float y = __shfl_up_sync(0xFFFFu, t, o);
            if (lane >= o) t = MX ? fmaxf(t, y) : (t + y);
        }
        ws[lane] = t;
    }
    __syncthreads();
    if (w > 0) {
        float pre = ws[w-1];
        x = MX ? fmaxf(x, pre) : (x + pre);
    }
    return x;
}

// ---------------- K1: fused prefix pipeline (R11 version) ----------
__global__ __launch_bounds__(512) void k_pre(const float* __restrict__ x,
                                             const float* __restrict__ w,
                                             const float* __restrict__ bl) {
    __shared__ float sl[512];
    __shared__ float se[512];
    __shared__ float sr[512];
    __shared__ float sP[512];
    __shared__ float sPre[128];
    __shared__ float sAgg[128];
    __shared__ float ws[16];
    __shared__ float sbc[2];
    int c = blockIdx.x, b = blockIdx.y;
    int bc = b*NCH + c;
    int tid = threadIdx.x, lane = tid & 31, wid = tid >> 5;
    size_t base = (size_t)b*LTOK + (size_t)c*BSB;

    // --- logits ---
    float4 wv = *(const float4*)&w[lane*4];
    float bb = bl[0];
    for (int r0 = wid; r0 < 512; r0 += 16) {
        float4 xv = *(const float4*)&x[(base + r0)*DD + lane*4];
        float s = xv.x*wv.x + xv.y*wv.y + xv.z*wv.z + xv.w*wv.w;
        #pragma unroll
        for (int o = 16; o; o >>= 1) s += __shfl_xor_sync(~0u, s, o);
        if (lane == 0) {
            float z = s + bb;
            sl[r0] = z / (1.f + expf(-z));
        }
    }
    __syncthreads();

    // --- inclusive cummax + max lookback ---
    float l = sl[tid];
    float lm = iscan512<true>(l, ws);
    if (tid == 511) sbc[0] = lm;
    __syncthreads();
    if (tid == 0) {
        float own = sbc[0];
        g_aggmax[bc] = own;
        __threadfence();
        st_release(&g_f1[bc], 1);
        float pre = -INFINITY;
        int j = c - 1;
        while (j >= 0) {
            unsigned f;
            do { f = ld_acquire(&g_f1[b*NCH + j]); } while (f == 0);
            if (f == 2) { pre = fmaxf(pre, g_incmax[b*NCH + j]); break; }
            pre = fmaxf(pre, g_aggmax[b*NCH + j]);
            j--;
        }
        g_incmax[bc] = fmaxf(pre, own);
        __threadfence();
        st_release(&g_f1[bc], 2);
        sbc[1] = pre;
    }
    __syncthreads();
    float preM = sbc[1];

    // --- e = exp(l - runmax), cumsum + sum lookback ---
    float M = fmaxf(lm, preM);
    float e = expf(l - M);
    se[tid] = e;
    float cs = iscan512<false>(e, ws);
    if (tid == 511) sbc[0] = cs;
    __syncthreads();
    if (tid == 0) {
        float own = sbc[0];
        g_aggsum[bc] = own;
        __threadfence();
        st_release(&g_f2[bc], 1);
        float pre = 0.f;
        int j = c - 1;
        while (j >= 0) {
            unsigned f;
            do { f = ld_acquire(&g_f2[b*NCH + j]); } while (f == 0);
            if (f == 2) { pre += g_incsum[b*NCH + j]; break; }
            pre += g_aggsum[b*NCH + j];
            j--;
        }
        g_incsum[bc] = pre + own;
        __threadfence();
        st_release(&g_f2[bc], 2);
        sbc[1] = pre;
    }
    __syncthreads();
    float preS = sbc[1];
    sr[tid] = 1.f / (cs + preS);
    __syncthreads();

    // --- channel partial sums of e*x ---
    int d = tid & 127, q = tid >> 7;
    const float* xq = x + (base + q*128)*DD + d;
    {
        float acc = 0.f;
        #pragma unroll 4
        for (int t = 0; t < 128; t++) acc += se[q*128 + t] * xq[(size_t)t*DD];
        sP[q*128 + d] = acc;
    }
    __syncthreads();
    if (tid < 128) {
        float v = sP[d] + sP[128 + d] + sP[256 + d] + sP[384 + d];
        g_aggch[bc*DD + d] = v;
        sAgg[d] = v;
        __threadfence();
    }
    __syncthreads();
    if (tid == 0) st_release(&g_f3[bc], 1);

    // --- channel vector lookback ---
    if (tid < 128) {
        float pre = 0.f;
        int j = c - 1;
        while (j >= 0) {
            unsigned f;
            do { f = ld_acquire(&g_f3[b*NCH + j]); } while (f == 0);
            if (f == 2) { pre += g_incch[(b*NCH + j)*DD + d]; break; }
            pre += g_aggch[(b*NCH + j)*DD + d];
            j--;
        }
        g_incch[bc*DD + d] = pre + sAgg[d];
        sPre[d] = pre;
        __threadfence();
    }
    __syncthreads();
    if (tid == 0) st_release(&g_f3[bc], 2);

    // --- final: prefix = cumsum(e*x)*r + x -> fp16 hi/lo ---
    float run = sPre[d];
    for (int qq = 0; qq < q; qq++) run += sP[qq*128 + d];
    __half* ph = g_ph + (base + q*128)*DD + d;
    __half* pl = g_pl + (base + q*128)*DD + d;
    #pragma unroll 4
    for (int t = 0; t < 128; t++) {
        float xv = xq[(size_t)t*DD];
        run += se[q*128 + t] * xv;
        float pv = run * sr[q*128 + t] + xv;
        __half h = __float2half(pv);
        ph[(size_t)t*DD] = h;
        pl[(size_t)t*DD] = __float2half(pv - __half2float(h));
    }
}

// ---------------- K4: conv1d fp16 single-pass, 2 CTAs/SM, fp16 output ----------
#define PITCH 272
#define A_OFF 0
#define W_OFF 36224
#define WSZ   34816
#define CONV_SMEM (W_OFF + 2*WSZ)    // 105856
__device__ __forceinline__ void conv_issueW(int k, uint32_t dstbase, int tid) {
    #pragma unroll
    for (int u = 0; u < 8; u++) {
        int t = tid + u*256;
        int o = t >> 4, cc = (t & 15) << 3;
        cpa16(dstbase + o*PITCH + cc*2, g_wh + (((size_t)(k*128 + o)) << 7) + cc);
    }
}
__global__ __launch_bounds__(256, 2) void k_conv() {
    extern __shared__ char sm[];
    uint32_t sb = smem_u32(sm);
    int tid = threadIdx.x, lane = tid & 31, wid = tid >> 5;
    int wm = wid >> 1, wn = wid & 1;
    int nb = blockIdx.x >> 2;
    int p0loc = (blockIdx.x & 3) << 7;
    int lr = lane & 15, lh = lane >> 4;

    float c[2][8][4];
    #pragma unroll
    for (int mt = 0; mt < 2; mt++)
        #pragma unroll
        for (int nt = 0; nt < 8; nt++)
            #pragma unroll
            for (int v = 0; v < 4; v++) c[mt][nt][v] = 0.f;

    for (int t = tid; t < 133*16; t += 256) {
        int r = t >> 4, cc = (t & 15) << 3;
        int qq = p0loc + r - 2;
        const void* src = g_ph;
        int sz = 0;
        if (qq >= 0 && qq < 512) {
            src = g_ph + ((((size_t)nb << 9) + qq) << 7) + cc;
            sz = 16;
        }
        cpa16z(sb + A_OFF + r*PITCH + cc*2, src, sz);
    }
    CPA_COMMIT();
    conv_issueW(0, sb + W_OFF, tid);
    CPA_COMMIT();
    conv_issueW(1, sb + W_OFF + WSZ, tid);
    CPA_COMMIT();
    CPA_WAIT(1);
    __syncthreads();
    #pragma unroll
    for (int s = 0; s < KW; s++) {
        uint32_t abase = sb + A_OFF + (wm*32 + s + lr)*PITCH + lh*16;
        uint32_t bbase = sb + W_OFF + (s & 1)*WSZ + (wn*64 + lr)*PITCH + lh*16;
        #pragma unroll
        for (int kc = 0; kc < 8; kc++) {
            uint32_t a[2][4];
            ldsm_x4(a[0], abase + kc*32);
            ldsm_x4(a[1], abase + kc*32 + 16*PITCH);
            #pragma unroll
            for (int ntp = 0; ntp < 4; ntp++) {
                uint32_t bf[4];
                ldsm_x4(bf, bbase + ntp*16*PITCH + kc*32);
                #pragma unroll
                for (int mt = 0; mt < 2; mt++) {
                    mma16816(c[mt][2*ntp],     a[mt], bf[0], bf[2]);
                    mma16816(c[mt][2*ntp + 1], a[mt], bf[1], bf[3]);
                }
            }
        }
        __syncthreads();
        if (s + 2 < KW) {
            conv_issueW(s + 2, sb + W_OFF + (s & 1)*WSZ, tid);
            CPA_COMMIT();
        }
        if (s + 1 < KW) {
            CPA_WAIT(1);
            __syncthreads();
        }
    }
    CPA_WAIT(0);
    __syncthreads();

    // epilogue: bias, fp16 store, fused per-block channel max (max in fp32)
    __shared__ float scb[128];
    // bias needs conv_b: read from constant-ish source — pass via g_pas? No:
    // conv bias is all-zeros per setup, but do it properly via param below.
    // (bias applied in k_conv via kernel arg — see launch)
    (void)scb;
    const float* cb = (const float*)0;  // placeholder (unused path)
    // NOTE: real bias handled by k_conv_bias version below
    // -- unreachable --
    (void)cb;
}

// real conv kernel with bias arg (the above stub is unused)
__global__ __launch_bounds__(256, 2) void k_conv2(const float* __restrict__ cb) {
    extern __shared__ char sm[];
    uint32_t sb = smem_u32(sm);
    int tid = threadIdx.x, lane = tid & 31, wid = tid >> 5;
    int wm = wid >> 1, wn = wid & 1;
    int nb = blockIdx.x >> 2;
    int p0loc = (blockIdx.x & 3) << 7;
    int lr = lane & 15, lh = lane >> 4;

    float c[2][8][4];
    #pragma unroll
    for (int mt = 0; mt < 2; mt++)
        #pragma unroll
        for (int nt = 0; nt < 8; nt++)
            #pragma unroll
            for (int v = 0; v < 4; v++) c[mt][nt][v] = 0.f;

    for (int t = tid; t < 133*16; t += 256) {
        int r = t >> 4, cc = (t & 15) << 3;
        int qq = p0loc + r - 2;
        const void* src = g_ph;
        int sz = 0;
        if (qq >= 0 && qq < 512) {
            src = g_ph + ((((size_t)nb << 9) + qq) << 7) + cc;
            sz = 16;
        }
        cpa16z(sb + A_OFF + r*PITCH + cc*2, src, sz);
    }
    CPA_COMMIT();
    conv_issueW(0, sb + W_OFF, tid);
    CPA_COMMIT();
    conv_issueW(1, sb + W_OFF + WSZ, tid);
    CPA_COMMIT();
    CPA_WAIT(1);
    __syncthreads();
    #pragma unroll
    for (int s = 0; s < KW; s++) {
        uint32_t abase = sb + A_OFF + (wm*32 + s + lr)*PITCH + lh*16;
        uint32_t bbase = sb + W_OFF + (s & 1)*WSZ + (wn*64 + lr)*PITCH + lh*16;
        #pragma unroll
        for (int kc = 0; kc < 8; kc++) {
            uint32_t a[2][4];
            ldsm_x4(a[0], abase + kc*32);
            ldsm_x4(a[1], abase + kc*32 + 16*PITCH);
            #pragma unroll
            for (int ntp = 0; ntp < 4; ntp++) {
                uint32_t bf[4];
                ldsm_x4(bf, bbase + ntp*16*PITCH + kc*32);
                #pragma unroll
                for (int mt = 0; mt < 2; mt++) {
                    mma16816(c[mt][2*ntp],     a[mt], bf[0], bf[2]);
                    mma16816(c[mt][2*ntp + 1], a[mt], bf[1], bf[3]);
                }
            }
        }
        __syncthreads();
        if (s + 2 < KW) {
            conv_issueW(s + 2, sb + W_OFF + (s & 1)*WSZ, tid);
            CPA_COMMIT();
        }
        if (s + 1 < KW) {
            CPA_WAIT(1);
            __syncthreads();
        }
    }
    CPA_WAIT(0);
    __syncthreads();

    int pbase = nb*512 + p0loc + wm*32 + (lane >> 2);
    #pragma unroll
    for (int nt = 0; nt < 8; nt++) {
        int col = wn*64 + nt*8 + (lane & 3)*2;
        float2 b2 = *(const float2*)(cb + col);
        float mx = -INFINITY, my = -INFINITY;
        #pragma unroll
        for (int mt = 0; mt < 2; mt++) {
            float x0 = c[mt][nt][0] + b2.x, y0 = c[mt][nt][1] + b2.y;
            float x1 = c[mt][nt][2] + b2.x, y1 = c[mt][nt][3] + b2.y;
            int row = pbase + mt*16;
            *(__half2*)(g_convh + ((size_t)row << 7) + col)       = __floats2half2_rn(x0, y0);
            *(__half2*)(g_convh + ((size_t)(row + 8) << 7) + col) = __floats2half2_rn(x1, y1);
            mx = fmaxf(mx, fmaxf(x0, x1));
            my = fmaxf(my, fmaxf(y0, y1));
        }
        #pragma unroll
        for (int o = 4; o < 32; o <<= 1) {
            mx = fmaxf(mx, __shfl_xor_sync(~0u, mx, o));
            my = fmaxf(my, __shfl_xor_sync(~0u, my, o));
        }
        if (lane < 4) {
            int cg = wn*64 + nt*8 + lane*2;
            atomicMax(&g_repr[nb*DD + cg],     enc_f(mx));
            atomicMax(&g_repr[nb*DD + cg + 1], enc_f(my));
        }
    }
}

// ---------------- K6a: a_s phase A — split softmax partials (fp16 KV, cp.async) ----
#define ATTNS_SMEM (128*128*2)   // 32 KB
__global__ __launch_bounds__(256, 4) void k_attn_s1() {
    extern __shared__ __half svh[];      // 128 rows x 128 ch fp16
    __shared__ float ss[128];
    __shared__ float red[256];
    int id = blockIdx.x;
    int n = id >> 2, qq = id & 3;
    int tid = threadIdx.x, lane = tid & 31, wid = tid >> 5;
    int d = tid & 127, h = tid >> 7;
    uint32_t sb = smem_u32(svh);
    const __half* kv = g_convh + ((size_t)n*BSB + qq*128)*DD;
    #pragma unroll
    for (int u = 0; u < 8; u++) {
        int i = (tid + u*256) * 8;       // half index, 16B chunks
        cpa16(sb + i*2, kv + i);
    }
    CPA_COMMIT();
    float4 q4;
    q4.x = dec_f(g_repr[n*DD + lane*4 + 0]);
    q4.y = dec_f(g_repr[n*DD + lane*4 + 1]);
    q4.z = dec_f(g_repr[n*DD + lane*4 + 2]);
    q4.w = dec_f(g_repr[n*DD + lane*4 + 3]);
    CPA_WAIT(0);
    __syncthreads();
    // scores: 8 warps x 16 rows
    const uint32_t* sv32 = (const uint32_t*)svh;
    for (int j = wid; j < 128; j += 8) {
        uint32_t u0 = sv32[j*64 + lane*2];
        uint32_t u1 = sv32[j*64 + lane*2 + 1];
        float2 k0 = __half22float2(*(__half2*)&u0);
        float2 k1 = __half22float2(*(__half2*)&u1);
        float p = q4.x*k0.x + q4.y*k0.y + q4.z*k1.x + q4.w*k1.y;
        #pragma unroll
        for (int o = 16; o; o >>= 1) p += __shfl_xor_sync(~0u, p, o);
        if (lane == 0) ss[j] = p * SCALEF;
    }
    __syncthreads();
    red[tid] = (tid < 128) ? ss[tid] : -INFINITY;
    __syncthreads();
    for (int st = 128; st; st >>= 1) { if (tid < st) red[tid] = fmaxf(red[tid], red[tid+st]); __syncthreads(); }
    float m = red[0];
    __syncthreads();
    float ev = 0.f;
    if (tid < 128) { ev = expf(ss[tid] - m); ss[tid] = ev; }
    red[tid] = ev;
    __syncthreads();
    for (int st = 128; st; st >>= 1) { if (tid < st) red[tid] += red[tid+st]; __syncthreads(); }
    float S = red[0];
    __syncthreads();
    float acc = 0.f;
    #pragma unroll 4
    for (int t = 0; t < 64; t++) {
        int row = h*64 + t;
        acc += ss[row] * __half2float(svh[row*DD + d]);
    }
    red[tid] = acc;
    __syncthreads();
    if (tid < 128) g_pas[id*DD + tid] = red[tid] + red[tid + 128];
    if (tid == 0) { g_pm[id] = m; g_psum[id] = S; }
}

// ---------------- K_tail: combine a_s + a_o + fusion GEMV ----------------
__global__ void k_tail(const float* __restrict__ fw, const float* __restrict__ fb,
                       float* __restrict__ out, int out_size) {
    int n = blockIdx.x, tid = threadIdx.x;  // 128 threads
    int lane = tid & 31, w = tid >> 5;
    int bq = n >> 6, c = n & 63;
    __shared__ float f[384];
    __shared__ float s[128];
    __shared__ float red[128];

    // a_s combine
    {
        float m0 = g_pm[n*4+0], m1 = g_pm[n*4+1], m2 = g_pm[n*4+2], m3 = g_pm[n*4+3];
        float M = fmaxf(fmaxf(m0, m1), fmaxf(m2, m3));
        float w0 = expf(m0 - M), w1 = expf(m1 - M), w2 = expf(m2 - M), w3 = expf(m3 - M);
        float S = w0*g_psum[n*4+0] + w1*g_psum[n*4+1] + w2*g_psum[n*4+2] + w3*g_psum[n*4+3];
        float v = w0*g_pas[(n*4+0)*DD + tid] + w1*g_pas[(n*4+1)*DD + tid]
                + w2*g_pas[(n*4+2)*DD + tid] + w3*g_pas[(n*4+3)*DD + tid];
        f[tid] = v / S;
    }
    f[256 + tid] = dec_f(g_repr[n*DD + tid]);

    // a_o
    float qa[4];
    #pragma unroll
    for (int q = 0; q < 4; q++) qa[q] = dec_f(g_repr[n*DD + lane*4 + q]);
    for (int j = w; j < 128; j += 4) {
        int tt = 448 + c*BSB + j; if (tt > LTOK-1) tt = LTOK-1;
        size_t ro = ((size_t)bq*LTOK + tt) << 7;
        float p = 0.f;
        #pragma unroll
        for (int q = 0; q < 4; q++) {
            int chn = lane*4 + q;
            float kvv = __half2float(g_ph[ro + chn]) + __half2float(g_pl[ro + chn]);
            p += qa[q] * kvv;
        }
        #pragma unroll
        for (int o = 16; o; o >>= 1) p += __shfl_xor_sync(~0u, p, o);
        if (lane == 0) s[j] = p * SCALEF;
    }
    __syncthreads();
    red[tid] = s[tid]; __syncthreads();
    for (int st = 64; st; st >>= 1) { if (tid < st) red[tid] = fmaxf(red[tid], red[tid+st]); __syncthreads(); }
    float M = red[0]; __syncthreads();
    float e = expf(s[tid] - M); s[tid] = e;
    red[tid] = e; __syncthreads();
    for (int st = 64; st; st >>= 1) { if (tid < st) red[tid] += red[tid+st]; __syncthreads(); }
    float SUM = red[0]; __syncthreads();
    float acc = 0.f;
    for (int j = 0; j < 128; j++) {
        int tt = 448 + c*BSB + j; if (tt > LTOK-1) tt = LTOK-1;
        size_t ro = ((size_t)bq*LTOK + tt) << 7;
        acc += s[j] * (__half2float(g_ph[ro + tid]) + __half2float(g_pl[ro + tid]));
    }
    f[128 + tid] = acc / SUM;
    __syncthreads();

    // fusion GEMV
    float accF = fb[tid];
    #pragma unroll 4
    for (int i = 0; i < 384; i++) accF += f[i] * fw[i*DD + tid];
    for (int off = 0; off + NBL*DD <= out_size; off += NBL*DD)
        out[off + n*DD + tid] = accF;
}

// ---------------- launch ----------------
extern "C" void kernel_launch(void* const* d_in, const int* in_sizes, int n_in,
                              void* d_out, int out_size) {
    const float* x        = (const float*)d_in[0];
    const float* w_lw     = (const float*)d_in[1];
    const float* b_lw     = (const float*)d_in[2];
    const float* conv_w   = (const float*)d_in[3];
    const float* conv_b   = (const float*)d_in[4];
    const float* fusion_w = (const float*)d_in[5];
    const float* fusion_b = (const float*)d_in[6];
    float* out = (float*)d_out;

    cudaFuncSetAttribute(k_conv2, cudaFuncAttributeMaxDynamicSharedMemorySize, CONV_SMEM);
    cudaFuncSetAttribute(k_attn_s1, cudaFuncAttributeMaxDynamicSharedMemorySize, ATTNS_SMEM);

    k_init<<<96, 1024>>>(conv_w);
    k_pre<<<dim3(NCH, BB), 512>>>(x, w_lw, b_lw);
    k_conv2<<<2048, 256, CONV_SMEM>>>(conv_b);
    k_attn_s1<<<NBL*4, 256, ATTNS_SMEM>>>();
    k_tail<<<NBL, 128>>>(fusion_w, fusion_b, out, out_size);
}

// round 15
// speedup vs baseline: 1.3076x; 1.0156x over previous
#include <cuda_runtime.h>
#include <cuda_fp16.h>
#include <math.h>
#include <stdint.h>

#define BB   8
#define LTOK 32768
#define DD   128
#define BSB  512
#define NBL  512
#define KW   6
#define NCH  64
#define SCALEF 0.08838834764831845f

// ---------------- device scratch ----------------
__device__ __align__(16) __half g_ph[(size_t)BB*LTOK*DD];    // prefix hi (fp16)
__device__ __align__(16) __half g_pl[(size_t)BB*LTOK*DD];    // prefix lo (fp16)
__device__ __align__(16) __half g_convh[(size_t)NBL*BSB*DD]; // conv out (fp16)
__device__ unsigned g_repr[NBL*DD];
__device__ __align__(16) __half g_wh[KW*DD*DD];  // [k][o][i], fp16
// decoupled-lookback state (agg-only)
__device__ float    g_aggmax[BB*NCH];
__device__ float    g_aggsum[BB*NCH];
__device__ float    g_aggch[BB*NCH*DD];
__device__ unsigned g_f1[BB*NCH], g_f2[BB*NCH], g_f3[BB*NCH];
// split-softmax partials (4 per block)
__device__ float    g_pm[NBL*4], g_psum[NBL*4];
__device__ float    g_pas[NBL*4*DD];

// ---------------- helpers ----------------
__device__ __forceinline__ unsigned enc_f(float f) {
    unsigned u = __float_as_uint(f);
    return (u & 0x80000000u) ? ~u : (u | 0x80000000u);
}
__device__ __forceinline__ float dec_f(unsigned u) {
    u = (u & 0x80000000u) ? (u & 0x7fffffffu) : ~u;
    return __uint_as_float(u);
}
__device__ __forceinline__ uint32_t smem_u32(const void* p) {
    uint32_t a;
    asm("{ .reg .u64 t; cvta.to.shared.u64 t, %1; cvt.u32.u64 %0, t; }" : "=r"(a) : "l"(p));
    return a;
}
__device__ __forceinline__ void st_release(unsigned* p, unsigned v) {
    asm volatile("st.release.gpu.u32 [%0], %1;" :: "l"(p), "r"(v) : "memory");
}
__device__ __forceinline__ unsigned ld_acquire(unsigned* p) {
    unsigned v;
    asm volatile("ld.acquire.gpu.u32 %0, [%1];" : "=r"(v) : "l"(p) : "memory");
    return v;
}
__device__ __forceinline__ void ldsm_x4(uint32_t* r, uint32_t addr) {
    asm volatile("ldmatrix.sync.aligned.m8n8.x4.shared.b16 {%0,%1,%2,%3}, [%4];"
        : "=r"(r[0]), "=r"(r[1]), "=r"(r[2]), "=r"(r[3]) : "r"(addr));
}
__device__ __forceinline__ void mma16816(float* c, const uint32_t* a, uint32_t b0, uint32_t b1) {
    asm volatile(
        "mma.sync.aligned.m16n8k16.row.col.f32.f16.f16.f32 "
        "{%0,%1,%2,%3}, {%4,%5,%6,%7}, {%8,%9}, {%0,%1,%2,%3};"
        : "+f"(c[0]), "+f"(c[1]), "+f"(c[2]), "+f"(c[3])
        : "r"(a[0]), "r"(a[1]), "r"(a[2]), "r"(a[3]), "r"(b0), "r"(b1));
}
__device__ __forceinline__ void cpa16(uint32_t dst, const void* src) {
    asm volatile("cp.async.cg.shared.global [%0], [%1], 16;" :: "r"(dst), "l"(src) : "memory");
}
__device__ __forceinline__ void cpa16z(uint32_t dst, const void* src, int srcsize) {
    asm volatile("cp.async.cg.shared.global [%0], [%1], 16, %2;" :: "r"(dst), "l"(src), "r"(srcsize) : "memory");
}
#define CPA_COMMIT() asm volatile("cp.async.commit_group;" ::: "memory")
#define CPA_WAIT(n)  asm volatile("cp.async.wait_group %0;" :: "n"(n) : "memory")

// ---------------- K0: weights -> fp16 [k][o][i] + init repr/flags ----------------
__global__ void k_init(const float* __restrict__ cw) {
    int idx = blockIdx.x * blockDim.x + threadIdx.x;
    if (idx < KW*DD*DD) {
        int i = idx & 127;
        int r = idx >> 7;
        int o = r & 127;
        int kk = r >> 7;
        g_wh[idx] = __float2half(cw[o*768 + i*6 + kk]);
    }
    if (idx < NBL*DD) g_repr[idx] = 0u;
    if (idx < BB*NCH) { g_f1[idx] = 0u; g_f2[idx] = 0u; g_f3[idx] = 0u; }
}

// ---------------- 512-thread inclusive scan ----------------
template<bool MX>
__device__ __forceinline__ float iscan512(float v, float* ws) {
    int lane = threadIdx.x & 31, w = threadIdx.x >> 5;
    float x = v;
    #pragma unroll
    for (int o = 1; o < 32; o <<= 1) {
        float y = __shfl_up_sync(~0u, x, o);
        if (lane >= o) x = MX ? fmaxf(x, y) : (x + y);
    }
    if (lane == 31) ws[w] = x;
    __syncthreads();
    if (w == 0 && lane < 16) {
        float t = ws[lane];
        #pragma unroll
        for (int o = 1; o < 16; o <<= 1) {
            float y = __shfl_up_sync(0xFFFFu, t, o);
            if (lane >= o) t = MX ? fmaxf(t, y) : (t + y);
        }
        ws[lane] = t;
    }
    __syncthreads();
    if (w > 0) {
        float pre = ws[w-1];
        x = MX ? fmaxf(x, pre) : (x + pre);
    }
    return x;
}

// warp-parallel agg-only lookback (32 predecessors per dependent round)
template<bool MX>
__device__ __forceinline__ float wlook(int b, int c, unsigned* flags, float* aggs) {
    int lane = threadIdx.x & 31;
    const float ID = MX ? -INFINITY : 0.f;
    float pre = ID;
    int rounds = (c + 31) >> 5;
    for (int r = 0; r < rounds; r++) {
        int j = c - 1 - lane - (r << 5);
        float v = ID;
        if (j >= 0) {
            unsigned f;
            do { f = ld_acquire(&flags[b*NCH + j]); } while (f == 0);
            v = aggs[b*NCH + j];
        }
        pre = MX ? fmaxf(pre, v) : (pre + v);
    }
    #pragma unroll
    for (int o = 16; o; o >>= 1) {
        float y = __shfl_xor_sync(~0u, pre, o);
        pre = MX ? fmaxf(pre, y) : (pre + y);
    }
    return pre;
}

// ---------------- K1: fused prefix pipeline (agg-only lookback) ----------
__global__ __launch_bounds__(512) void k_pre(const float* __restrict__ x,
                                             const float* __restrict__ w,
                                             const float* __restrict__ bl) {
    __shared__ float sl[512];
    __shared__ float se[512];
    __shared__ float sr[512];
    __shared__ float sP[512];
    __shared__ float sV[512];
    __shared__ float sPre[128];
    __shared__ float ws[16];
    __shared__ float sbc[2];
    int c = blockIdx.x, b = blockIdx.y;
    int bc = b*NCH + c;
    int tid = threadIdx.x, lane = tid & 31, wid = tid >> 5;
    size_t base = (size_t)b*LTOK + (size_t)c*BSB;

    // --- logits (x pass 1) ---
    float4 wv = *(const float4*)&w[lane*4];
    float bb = bl[0];
    for (int r0 = wid; r0 < 512; r0 += 16) {
        float4 xv = *(const float4*)&x[(base + r0)*DD + lane*4];
        float s = xv.x*wv.x + xv.y*wv.y + xv.z*wv.z + xv.w*wv.w;
        #pragma unroll
        for (int o = 16; o; o >>= 1) s += __shfl_xor_sync(~0u, s, o);
        if (lane == 0) {
            float z = s + bb;
            sl[r0] = z / (1.f + expf(-z));
        }
    }
    __syncthreads();

    // --- inclusive cummax + max lookback (warp-parallel, agg-only) ---
    float l = sl[tid];
    float lm = iscan512<true>(l, ws);
    if (tid == 511) sbc[0] = lm;
    __syncthreads();
    if (tid < 32) {
        if (lane == 0) {
            g_aggmax[bc] = sbc[0];
            __threadfence();
            st_release(&g_f1[bc], 1);
        }
        __syncwarp();
        float pre = wlook<true>(b, c, g_f1, g_aggmax);
        if (lane == 0) sbc[1] = pre;
    }
    __syncthreads();
    float preM = sbc[1];

    // --- e = exp(l - runmax), cumsum + sum lookback ---
    float M = fmaxf(lm, preM);
    float e = expf(l - M);
    se[tid] = e;
    float cs = iscan512<false>(e, ws);
    if (tid == 511) sbc[0] = cs;
    __syncthreads();
    if (tid < 32) {
        if (lane == 0) {
            g_aggsum[bc] = sbc[0];
            __threadfence();
            st_release(&g_f2[bc], 1);
        }
        __syncwarp();
        float pre = wlook<false>(b, c, g_f2, g_aggsum);
        if (lane == 0) sbc[1] = pre;
    }
    __syncthreads();
    float preS = sbc[1];
    sr[tid] = 1.f / (cs + preS);
    __syncthreads();

    // --- channel partial sums of e*x (x pass 2) ---
    int d = tid & 127, q = tid >> 7;
    const float* xq = x + (base + q*128)*DD + d;
    {
        float acc = 0.f;
        #pragma unroll 4
        for (int t = 0; t < 128; t++) acc += se[q*128 + t] * xq[(size_t)t*DD];
        sP[q*128 + d] = acc;
    }
    __syncthreads();
    if (tid < 128) {
        g_aggch[bc*DD + d] = sP[d] + sP[128 + d] + sP[256 + d] + sP[384 + d];
        __threadfence();
    }
    __syncthreads();
    if (tid == 0) st_release(&g_f3[bc], 1);

    // --- channel vector lookback: stride-4 q-parallel, agg-only ---
    {
        float pre = 0.f;
        for (int j = c - 1 - q; j >= 0; j -= 4) {
            unsigned f;
            do { f = ld_acquire(&g_f3[b*NCH + j]); } while (f == 0);
            pre += g_aggch[(b*NCH + j)*DD + d];
        }
        sV[q*128 + d] = pre;
    }
    __syncthreads();
    if (tid < 128) sPre[tid] = sV[tid] + sV[128 + tid] + sV[256 + tid] + sV[384 + tid];
    __syncthreads();

    // --- final (x pass 3): prefix = cumsum(e*x)*r + x -> fp16 hi/lo ---
    float run = sPre[d];
    for (int qq = 0; qq < q; qq++) run += sP[qq*128 + d];
    __half* ph = g_ph + (base + q*128)*DD + d;
    __half* pl = g_pl + (base + q*128)*DD + d;
    #pragma unroll 4
    for (int t = 0; t < 128; t++) {
        float xv = xq[(size_t)t*DD];
        run += se[q*128 + t] * xv;
        float pv = run * sr[q*128 + t] + xv;
        __half h = __float2half(pv);
        ph[(size_t)t*DD] = h;
        pl[(size_t)t*DD] = __float2half(pv - __half2float(h));
    }
}

// ---------------- K4: conv1d fp16 single-pass, 2 CTAs/SM, fp16 output ----------
#define PITCH 272
#define A_OFF 0
#define W_OFF 36224
#define WSZ   34816
#define CONV_SMEM (W_OFF + 2*WSZ)    // 105856
__device__ __forceinline__ void conv_issueW(int k, uint32_t dstbase, int tid) {
    #pragma unroll
    for (int u = 0; u < 8; u++) {
        int t = tid + u*256;
        int o = t >> 4, cc = (t & 15) << 3;
        cpa16(dstbase + o*PITCH + cc*2, g_wh + (((size_t)(k*128 + o)) << 7) + cc);
    }
}
__global__ __launch_bounds__(256, 2) void k_conv2(const float* __restrict__ cb) {
    extern __shared__ char sm[];
    uint32_t sb = smem_u32(sm);
    int tid = threadIdx.x, lane = tid & 31, wid = tid >> 5;
    int wm = wid >> 1, wn = wid & 1;
    int nb = blockIdx.x >> 2;
    int p0loc = (blockIdx.x & 3) << 7;
    int lr = lane & 15, lh = lane >> 4;

    float c[2][8][4];
    #pragma unroll
    for (int mt = 0; mt < 2; mt++)
        #pragma unroll
        for (int nt = 0; nt < 8; nt++)
            #pragma unroll
            for (int v = 0; v < 4; v++) c[mt][nt][v] = 0.f;

    for (int t = tid; t < 133*16; t += 256) {
        int r = t >> 4, cc = (t & 15) << 3;
        int qq = p0loc + r - 2;
        const void* src = g_ph;
        int sz = 0;
        if (qq >= 0 && qq < 512) {
            src = g_ph + ((((size_t)nb << 9) + qq) << 7) + cc;
            sz = 16;
        }
        cpa16z(sb + A_OFF + r*PITCH + cc*2, src, sz);
    }
    CPA_COMMIT();
    conv_issueW(0, sb + W_OFF, tid);
    CPA_COMMIT();
    conv_issueW(1, sb + W_OFF + WSZ, tid);
    CPA_COMMIT();
    CPA_WAIT(1);
    __syncthreads();
    #pragma unroll
    for (int s = 0; s < KW; s++) {
        uint32_t abase = sb + A_OFF + (wm*32 + s + lr)*PITCH + lh*16;
        uint32_t bbase = sb + W_OFF + (s & 1)*WSZ + (wn*64 + lr)*PITCH + lh*16;
        #pragma unroll
        for (int kc = 0; kc < 8; kc++) {
            uint32_t a[2][4];
            ldsm_x4(a[0], abase + kc*32);
            ldsm_x4(a[1], abase + kc*32 + 16*PITCH);
            #pragma unroll
            for (int ntp = 0; ntp < 4; ntp++) {
                uint32_t bf[4];
                ldsm_x4(bf, bbase + ntp*16*PITCH + kc*32);
                #pragma unroll
                for (int mt = 0; mt < 2; mt++) {
                    mma16816(c[mt][2*ntp],     a[mt], bf[0], bf[2]);
                    mma16816(c[mt][2*ntp + 1], a[mt], bf[1], bf[3]);
                }
            }
        }
        __syncthreads();
        if (s + 2 < KW) {
            conv_issueW(s + 2, sb + W_OFF + (s & 1)*WSZ, tid);
            CPA_COMMIT();
        }
        if (s + 1 < KW) {
            CPA_WAIT(1);
            __syncthreads();
        }
    }
    CPA_WAIT(0);
    __syncthreads();

    int pbase = nb*512 + p0loc + wm*32 + (lane >> 2);
    #pragma unroll
    for (int nt = 0; nt < 8; nt++) {
        int col = wn*64 + nt*8 + (lane & 3)*2;
        float2 b2 = *(const float2*)(cb + col);
        float mx = -INFINITY, my = -INFINITY;
        #pragma unroll
        for (int mt = 0; mt < 2; mt++) {
            float x0 = c[mt][nt][0] + b2.x, y0 = c[mt][nt][1] + b2.y;
            float x1 = c[mt][nt][2] + b2.x, y1 = c[mt][nt][3] + b2.y;
            int row = pbase + mt*16;
            *(__half2*)(g_convh + ((size_t)row << 7) + col)       = __floats2half2_rn(x0, y0);
            *(__half2*)(g_convh + ((size_t)(row + 8) << 7) + col) = __floats2half2_rn(x1, y1);
            mx = fmaxf(mx, fmaxf(x0, x1));
            my = fmaxf(my, fmaxf(y0, y1));
        }
        #pragma unroll
        for (int o = 4; o < 32; o <<= 1) {
            mx = fmaxf(mx, __shfl_xor_sync(~0u, mx, o));
            my = fmaxf(my, __shfl_xor_sync(~0u, my, o));
        }
        if (lane < 4) {
            int cg = wn*64 + nt*8 + lane*2;
            atomicMax(&g_repr[nb*DD + cg],     enc_f(mx));
            atomicMax(&g_repr[nb*DD + cg + 1], enc_f(my));
        }
    }
}

// ---------------- K6a: a_s phase A — split softmax partials (fp16 KV, cp.async) ----
#define ATTNS_SMEM (128*128*2)   // 32 KB
__global__ __launch_bounds__(256, 4) void k_attn_s1() {
    extern __shared__ __half svh[];      // 128 rows x 128 ch fp16
    __shared__ float ss[128];
    __shared__ float red[256];
    int id = blockIdx.x;
    int n = id >> 2, qq = id & 3;
    int tid = threadIdx.x, lane = tid & 31, wid = tid >> 5;
    int d = tid & 127, h = tid >> 7;
    uint32_t sb = smem_u32(svh);
    const __half* kv = g_convh + ((size_t)n*BSB + qq*128)*DD;
    #pragma unroll
    for (int u = 0; u < 8; u++) {
        int i = (tid + u*256) * 8;
        cpa16(sb + i*2, kv + i);
    }
    CPA_COMMIT();
    float4 q4;
    q4.x = dec_f(g_repr[n*DD + lane*4 + 0]);
    q4.y = dec_f(g_repr[n*DD + lane*4 + 1]);
    q4.z = dec_f(g_repr[n*DD + lane*4 + 2]);
    q4.w = dec_f(g_repr[n*DD + lane*4 + 3]);
    CPA_WAIT(0);
    __syncthreads();
    const uint32_t* sv32 = (const uint32_t*)svh;
    for (int j = wid; j < 128; j += 8) {
        uint32_t u0 = sv32[j*64 + lane*2];
        uint32_t u1 = sv32[j*64 + lane*2 + 1];
        float2 k0 = __half22float2(*(__half2*)&u0);
        float2 k1 = __half22float2(*(__half2*)&u1);
        float p = q4.x*k0.x + q4.y*k0.y + q4.z*k1.x + q4.w*k1.y;
        #pragma unroll
        for (int o = 16; o; o >>= 1) p += __shfl_xor_sync(~0u, p, o);
        if (lane == 0) ss[j] = p * SCALEF;
    }
    __syncthreads();
    red[tid] = (tid < 128) ? ss[tid] : -INFINITY;
    __syncthreads();
    for (int st = 128; st; st >>= 1) { if (tid < st) red[tid] = fmaxf(red[tid], red[tid+st]); __syncthreads(); }
    float m = red[0];
    __syncthreads();
    float ev = 0.f;
    if (tid < 128) { ev = expf(ss[tid] - m); ss[tid] = ev; }
    red[tid] = ev;
    __syncthreads();
    for (int st = 128; st; st >>= 1) { if (tid < st) red[tid] += red[tid+st]; __syncthreads(); }
    float S = red[0];
    __syncthreads();
    float acc = 0.f;
    #pragma unroll 4
    for (int t = 0; t < 64; t++) {
        int row = h*64 + t;
        acc += ss[row] * __half2float(svh[row*DD + d]);
    }
    red[tid] = acc;
    __syncthreads();
    if (tid < 128) g_pas[id*DD + tid] = red[tid] + red[tid + 128];
    if (tid == 0) { g_pm[id] = m; g_psum[id] = S; }
}

// ---------------- K_tail: combine a_s + a_o + fusion GEMV ----------------
__global__ void k_tail(const float* __restrict__ fw, const float* __restrict__ fb,
                       float* __restrict__ out, int out_size) {
    int n = blockIdx.x, tid = threadIdx.x;  // 128 threads
    int lane = tid & 31, w = tid >> 5;
    int bq = n >> 6, c = n & 63;
    __shared__ float f[384];
    __shared__ float s[128];
    __shared__ float red[128];

    // a_s combine
    {
        float m0 = g_pm[n*4+0], m1 = g_pm[n*4+1], m2 = g_pm[n*4+2], m3 = g_pm[n*4+3];
        float M = fmaxf(fmaxf(m0, m1), fmaxf(m2, m3));
        float w0 = expf(m0 - M), w1 = expf(m1 - M), w2 = expf(m2 - M), w3 = expf(m3 - M);
        float S = w0*g_psum[n*4+0] + w1*g_psum[n*4+1] + w2*g_psum[n*4+2] + w3*g_psum[n*4+3];
        float v = w0*g_pas[(n*4+0)*DD + tid] + w1*g_pas[(n*4+1)*DD + tid]
                + w2*g_pas[(n*4+2)*DD + tid] + w3*g_pas[(n*4+3)*DD + tid];
        f[tid] = v / S;
    }
    f[256 + tid] = dec_f(g_repr[n*DD + tid]);

    // a_o
    float qa[4];
    #pragma unroll
    for (int q = 0; q < 4; q++) qa[q] = dec_f(g_repr[n*DD + lane*4 + q]);
    for (int j = w; j < 128; j += 4) {
        int tt = 448 + c*BSB + j; if (tt > LTOK-1) tt = LTOK-1;
        size_t ro = ((size_t)bq*LTOK + tt) << 7;
        float p = 0.f;
        #pragma unroll
        for (int q = 0; q < 4; q++) {
            int chn = lane*4 + q;
            float kvv = __half2float(g_ph[ro + chn]) + __half2float(g_pl[ro + chn]);
            p += qa[q] * kvv;
        }
        #pragma unroll
        for (int o = 16; o; o >>= 1) p += __shfl_xor_sync(~0u, p, o);
        if (lane == 0) s[j] = p * SCALEF;
    }
    __syncthreads();
    red[tid] = s[tid]; __syncthreads();
    for (int st = 64; st; st >>= 1) { if (tid < st) red[tid] = fmaxf(red[tid], red[tid+st]); __syncthreads(); }
    float M = red[0]; __syncthreads();
    float e = expf(s[tid] - M); s[tid] = e;
    red[tid] = e; __syncthreads();
    for (int st = 64; st; st >>= 1) { if (tid < st) red[tid] += red[tid+st]; __syncthreads(); }
    float SUM = red[0]; __syncthreads();
    float acc = 0.f;
    for (int j = 0; j < 128; j++) {
        int tt = 448 + c*BSB + j; if (tt > LTOK-1) tt = LTOK-1;
        size_t ro = ((size_t)bq*LTOK + tt) << 7;
        acc += s[j] * (__half2float(g_ph[ro + tid]) + __half2float(g_pl[ro + tid]));
    }
    f[128 + tid] = acc / SUM;
    __syncthreads();

    // fusion GEMV
    float accF = fb[tid];
    #pragma unroll 4
    for (int i = 0; i < 384; i++) accF += f[i] * fw[i*DD + tid];
    for (int off = 0; off + NBL*DD <= out_size; off += NBL*DD)
        out[off + n*DD + tid] = accF;
}

// ---------------- launch ----------------
extern "C" void kernel_launch(void* const* d_in, const int* in_sizes, int n_in,
                              void* d_out, int out_size) {
    const float* x        = (const float*)d_in[0];
    const float* w_lw     = (const float*)d_in[1];
    const float* b_lw     = (const float*)d_in[2];
    const float* conv_w   = (const float*)d_in[3];
    const float* conv_b   = (const float*)d_in[4];
    const float* fusion_w = (const float*)d_in[5];
    const float* fusion_b = (const float*)d_in[6];
    float* out = (float*)d_out;

    cudaFuncSetAttribute(k_conv2, cudaFuncAttributeMaxDynamicSharedMemorySize, CONV_SMEM);
    cudaFuncSetAttribute(k_attn_s1, cudaFuncAttributeMaxDynamicSharedMemorySize, ATTNS_SMEM);

    k_init<<<96, 1024>>>(conv_w);
    k_pre<<<dim3(NCH, BB), 512>>>(x, w_lw, b_lw);
    k_conv2<<<2048, 256, CONV_SMEM>>>(conv_b);
    k_attn_s1<<<NBL*4, 256, ATTNS_SMEM>>>();
    k_tail<<<NBL, 128>>>(fusion_w, fusion_b, out, out_size);
}